// round 3
// baseline (speedup 1.0000x reference)
#include <cuda_runtime.h>
#include <math_constants.h>

// ============================================================
// ChamferLoss fused single-kernel.
// s = q.b - 0.5|b|^2 via fma.rn.f32x2 (2 queries/op); min d^2 = qn - 2*max_j s.
// Cross-CTA min: unsigned atomicMax on ~bits(dsq) (identity = 0 => no init pass).
// Last CTA (ticket) does sqrt+sum, writes out, and resets state for next replay.
// ============================================================

#define THREADS 128
#define QPT 8            // queries per thread (4 packed pairs)
#define TCHUNK 512       // targets per SMEM tile (16 KB duplicated layout)
#define MAXPTS 16384

__device__ unsigned g_min[2 * MAXPTS];   // zero-init BSS; holds ~bits(min dsq)
__device__ unsigned g_ticket;            // zero-init

__device__ __forceinline__ unsigned long long pack2(float lo, float hi) {
    unsigned long long r;
    asm("mov.b64 %0, {%1, %2};" : "=l"(r) : "f"(lo), "f"(hi));
    return r;
}

__global__ void __launch_bounds__(THREADS)
chamfer_fused_kernel(const float* __restrict__ A, const float* __restrict__ B,
                     int N, int M, float* __restrict__ out)
{
    const int tid = threadIdx.x;
    const int dir = blockIdx.z;
    const float* __restrict__ P = dir ? B : A;   // queries
    const float* __restrict__ T = dir ? A : B;   // targets
    const int nq = dir ? M : N;
    const int nt = dir ? N : M;
    unsigned* minarr = g_min + dir * MAXPTS;

    // per target: {bx,bx},{by,by} | {bz,bz},{nhb,nhb}
    __shared__ ulonglong2 sv[TCHUNK * 2];        // 16 KB

    const int tbase = blockIdx.y * TCHUNK;
    if (tbase < nt) {
        const int nload = min(TCHUNK, nt - tbase);

        for (int j = tid; j < nload; j += THREADS) {
            float bx = T[(tbase + j) * 3 + 0];
            float by = T[(tbase + j) * 3 + 1];
            float bz = T[(tbase + j) * 3 + 2];
            float nhb = -0.5f * fmaf(bx, bx, fmaf(by, by, bz * bz));
            sv[2 * j]     = make_ulonglong2(pack2(bx, bx), pack2(by, by));
            sv[2 * j + 1] = make_ulonglong2(pack2(bz, bz), pack2(nhb, nhb));
        }
        __syncthreads();

        const int qbase = blockIdx.x * (THREADS * QPT) + tid;
        float qfx[QPT], qfy[QPT], qfz[QPT], qn[QPT], ms[QPT];
        #pragma unroll
        for (int q = 0; q < QPT; q++) {
            int qi = qbase + q * THREADS;
            int base = (qi < nq ? qi : 0) * 3;
            qfx[q] = P[base + 0];
            qfy[q] = P[base + 1];
            qfz[q] = P[base + 2];
            qn[q] = fmaf(qfx[q], qfx[q], fmaf(qfy[q], qfy[q], qfz[q] * qfz[q]));
            ms[q] = -CUDART_INF_F;
        }
        unsigned long long qx[QPT / 2], qy[QPT / 2], qz[QPT / 2];
        #pragma unroll
        for (int p = 0; p < QPT / 2; p++) {
            qx[p] = pack2(qfx[2 * p], qfx[2 * p + 1]);
            qy[p] = pack2(qfy[2 * p], qfy[2 * p + 1]);
            qz[p] = pack2(qfz[2 * p], qfz[2 * p + 1]);
        }

        // main loop: 2 LDS.128 + 12 FFMA2 + 8 FMNMX per target
        #pragma unroll 4
        for (int j = 0; j < nload; j++) {
            const ulonglong2 v0 = sv[2 * j];       // {bx,bx},{by,by}
            const ulonglong2 v1 = sv[2 * j + 1];   // {bz,bz},{nhb,nhb}
            #pragma unroll
            for (int p = 0; p < QPT / 2; p++) {
                unsigned long long t;
                asm("fma.rn.f32x2 %0, %1, %2, %3;"
                    : "=l"(t) : "l"(qz[p]), "l"(v1.x), "l"(v1.y));
                asm("fma.rn.f32x2 %0, %1, %2, %3;"
                    : "=l"(t) : "l"(qy[p]), "l"(v0.y), "l"(t));
                asm("fma.rn.f32x2 %0, %1, %2, %3;"
                    : "=l"(t) : "l"(qx[p]), "l"(v0.x), "l"(t));
                float s0, s1;
                asm("mov.b64 {%0, %1}, %2;" : "=f"(s0), "=f"(s1) : "l"(t));
                ms[2 * p]     = fmaxf(ms[2 * p],     s0);
                ms[2 * p + 1] = fmaxf(ms[2 * p + 1], s1);
            }
        }

        // dsq = max(qn - 2*max_s, 0); min across CTAs == max of ~bits (dsq >= 0)
        #pragma unroll
        for (int q = 0; q < QPT; q++) {
            int qi = qbase + q * THREADS;
            if (qi < nq) {
                float dsq = fmaxf(fmaf(-2.0f, ms[q], qn[q]), 0.0f);
                atomicMax(&minarr[qi], ~(unsigned)__float_as_int(dsq));
            }
        }
    }

    // ---- ticket: last CTA reduces ----
    __threadfence();
    __shared__ unsigned s_last;
    __shared__ float s_red[THREADS / 32];
    const unsigned total_ctas = gridDim.x * gridDim.y * gridDim.z;
    if (tid == 0)
        s_last = (atomicAdd(&g_ticket, 1u) == total_ctas - 1u);
    __syncthreads();
    if (!s_last) return;

    float acc = 0.0f;
    #pragma unroll 4
    for (int i = tid; i < N; i += THREADS) {
        unsigned u = g_min[i];
        acc += sqrtf(__int_as_float((int)~u));
        g_min[i] = 0u;                     // reset for next graph replay
    }
    #pragma unroll 4
    for (int i = tid; i < M; i += THREADS) {
        unsigned u = g_min[MAXPTS + i];
        acc += sqrtf(__int_as_float((int)~u));
        g_min[MAXPTS + i] = 0u;
    }

    #pragma unroll
    for (int o = 16; o > 0; o >>= 1)
        acc += __shfl_down_sync(0xFFFFFFFFu, acc, o);
    if ((tid & 31) == 0) s_red[tid >> 5] = acc;
    __syncthreads();
    if (tid == 0) {
        float v = 0.0f;
        #pragma unroll
        for (int w = 0; w < THREADS / 32; w++) v += s_red[w];
        out[0] = v * 0.001f;
        g_ticket = 0u;                     // reset ticket for next replay
    }
}

extern "C" void kernel_launch(void* const* d_in, const int* in_sizes, int n_in,
                              void* d_out, int out_size)
{
    const float* A = (const float*)d_in[0];   // target_pc [N,3]
    const float* B = (const float*)d_in[1];   // output_pc [M,3]
    const int N = in_sizes[0] / 3;
    const int M = in_sizes[1] / 3;

    const int qspan = THREADS * QPT;                 // 1024 queries / CTA
    const int maxn = (N > M) ? N : M;
    dim3 grid((maxn + qspan - 1) / qspan,            // 16
              (maxn + TCHUNK - 1) / TCHUNK,          // 32
              2);                                    // both directions
    chamfer_fused_kernel<<<grid, THREADS>>>(A, B, N, M, (float*)d_out);
}

// round 4
// speedup vs baseline: 1.3399x; 1.3399x over previous
#include <cuda_runtime.h>
#include <math_constants.h>

// ============================================================
// ChamferLoss fused single-kernel (round-2 inner loop, balanced grid).
// s = q.b - 0.5|b|^2 via fma.rn.f32x2 (2 queries/op); min d^2 = qn - 2*max_j s.
// Cross-CTA min: unsigned atomicMax on ~bits(dsq) (identity 0 => no init pass).
// Last CTA (ticket) does sqrt+sum, writes out, resets state for next replay.
// Grid = 8 qblocks x 37 chunks x 2 dirs = 592 = 148 SMs x 4 CTAs exactly.
// ============================================================

#define THREADS 256
#define QPT 8            // queries per thread (4 packed pairs)
#define TCHUNK 443       // 37 chunks cover 16384 (37*443 = 16391)
#define NCHUNKS 37
#define MAXPTS 16384

__device__ unsigned g_min[2 * MAXPTS];   // zero-init BSS; holds ~bits(min dsq)
__device__ unsigned g_ticket;            // zero-init

__device__ __forceinline__ unsigned long long pack2(float lo, float hi) {
    unsigned long long r;
    asm("mov.b64 %0, {%1, %2};" : "=l"(r) : "f"(lo), "f"(hi));
    return r;
}
__device__ __forceinline__ void unpack2(unsigned long long v, float& lo, float& hi) {
    asm("mov.b64 {%0, %1}, %2;" : "=f"(lo), "=f"(hi) : "l"(v));
}
__device__ __forceinline__ unsigned long long fma2(unsigned long long a,
                                                   unsigned long long b,
                                                   unsigned long long c) {
    unsigned long long d;
    asm("fma.rn.f32x2 %0, %1, %2, %3;" : "=l"(d) : "l"(a), "l"(b), "l"(c));
    return d;
}

__global__ void __launch_bounds__(THREADS, 4)
chamfer_fused_kernel(const float* __restrict__ A, const float* __restrict__ B,
                     int N, int M, float* __restrict__ out)
{
    const int tid = threadIdx.x;
    const int dir = blockIdx.z;
    const float* __restrict__ P = dir ? B : A;   // queries
    const float* __restrict__ T = dir ? A : B;   // targets
    const int nq = dir ? M : N;
    const int nt = dir ? N : M;
    unsigned* minarr = g_min + dir * MAXPTS;

    // per target: {bx,bx},{by,by} | {bz,bz},{nhb,nhb}
    __shared__ ulonglong2 sv[TCHUNK * 2];        // ~14.2 KB

    const int tbase = blockIdx.y * TCHUNK;
    if (tbase < nt) {
        const int nload = min(TCHUNK, nt - tbase);

        for (int j = tid; j < nload; j += THREADS) {
            float bx = T[(tbase + j) * 3 + 0];
            float by = T[(tbase + j) * 3 + 1];
            float bz = T[(tbase + j) * 3 + 2];
            float nhb = -0.5f * fmaf(bx, bx, fmaf(by, by, bz * bz));
            sv[2 * j]     = make_ulonglong2(pack2(bx, bx), pack2(by, by));
            sv[2 * j + 1] = make_ulonglong2(pack2(bz, bz), pack2(nhb, nhb));
        }
        __syncthreads();

        // register-resident queries, packed in pairs
        const int qbase = blockIdx.x * (THREADS * QPT) + tid;
        float qfx[QPT], qfy[QPT], qfz[QPT], qn[QPT], ms[QPT];
        #pragma unroll
        for (int q = 0; q < QPT; q++) {
            int qi = qbase + q * THREADS;
            int base = (qi < nq ? qi : 0) * 3;
            qfx[q] = P[base + 0];
            qfy[q] = P[base + 1];
            qfz[q] = P[base + 2];
            qn[q] = fmaf(qfx[q], qfx[q], fmaf(qfy[q], qfy[q], qfz[q] * qfz[q]));
            ms[q] = -CUDART_INF_F;
        }
        unsigned long long qx[QPT / 2], qy[QPT / 2], qz[QPT / 2];
        #pragma unroll
        for (int p = 0; p < QPT / 2; p++) {
            qx[p] = pack2(qfx[2 * p], qfx[2 * p + 1]);
            qy[p] = pack2(qfy[2 * p], qfy[2 * p + 1]);
            qz[p] = pack2(qfz[2 * p], qfz[2 * p + 1]);
        }

        // main loop: 2 broadcast LDS.128 + 12 FFMA2 + 8 FMNMX per target
        #pragma unroll 2
        for (int j = 0; j < nload; j++) {
            const ulonglong2 v0 = sv[2 * j];       // {bx,bx},{by,by}
            const ulonglong2 v1 = sv[2 * j + 1];   // {bz,bz},{nhb,nhb}
            #pragma unroll
            for (int p = 0; p < QPT / 2; p++) {
                unsigned long long t = fma2(qz[p], v1.x, v1.y);  // qz*bz - .5|b|^2
                t = fma2(qy[p], v0.y, t);
                t = fma2(qx[p], v0.x, t);                        // s
                float s0, s1;
                unpack2(t, s0, s1);
                ms[2 * p]     = fmaxf(ms[2 * p],     s0);
                ms[2 * p + 1] = fmaxf(ms[2 * p + 1], s1);
            }
        }

        // dsq = max(qn - 2*max_s, 0); cross-CTA min == max of ~bits (dsq >= 0)
        #pragma unroll
        for (int q = 0; q < QPT; q++) {
            int qi = qbase + q * THREADS;
            if (qi < nq) {
                float dsq = fmaxf(fmaf(-2.0f, ms[q], qn[q]), 0.0f);
                atomicMax(&minarr[qi], ~(unsigned)__float_as_int(dsq));
            }
        }
    }

    // ---- ticket: last CTA reduces ----
    __threadfence();
    __shared__ unsigned s_last;
    __shared__ float s_red[THREADS / 32];
    const unsigned total_ctas = gridDim.x * gridDim.y * gridDim.z;
    if (tid == 0)
        s_last = (atomicAdd(&g_ticket, 1u) == total_ctas - 1u);
    __syncthreads();
    if (!s_last) return;

    float acc = 0.0f;
    #pragma unroll 4
    for (int i = tid; i < N; i += THREADS) {
        unsigned u = g_min[i];
        acc += sqrtf(__int_as_float((int)~u));
        g_min[i] = 0u;                     // reset for next graph replay
    }
    #pragma unroll 4
    for (int i = tid; i < M; i += THREADS) {
        unsigned u = g_min[MAXPTS + i];
        acc += sqrtf(__int_as_float((int)~u));
        g_min[MAXPTS + i] = 0u;
    }

    #pragma unroll
    for (int o = 16; o > 0; o >>= 1)
        acc += __shfl_down_sync(0xFFFFFFFFu, acc, o);
    if ((tid & 31) == 0) s_red[tid >> 5] = acc;
    __syncthreads();
    if (tid == 0) {
        float v = 0.0f;
        #pragma unroll
        for (int w = 0; w < THREADS / 32; w++) v += s_red[w];
        out[0] = v * 0.001f;
        g_ticket = 0u;                     // reset ticket for next replay
    }
}

extern "C" void kernel_launch(void* const* d_in, const int* in_sizes, int n_in,
                              void* d_out, int out_size)
{
    const float* A = (const float*)d_in[0];   // target_pc [N,3]
    const float* B = (const float*)d_in[1];   // output_pc [M,3]
    const int N = in_sizes[0] / 3;
    const int M = in_sizes[1] / 3;

    dim3 grid(8, NCHUNKS, 2);                 // 8*37*2 = 592 = 148 SMs * 4
    chamfer_fused_kernel<<<grid, THREADS>>>(A, B, N, M, (float*)d_out);
}

// round 5
// speedup vs baseline: 1.5826x; 1.1811x over previous
#include <cuda_runtime.h>
#include <math_constants.h>

// ============================================================
// ChamferLoss, 2 launches.
// s = q.b - 0.5|b|^2 via fma.rn.f32x2 (2 queries/op); min d^2 = qn - 2*max_j s.
// Cross-CTA min: atomicMax on ~bits(dsq) (identity 0 -> no init kernel);
// reduce kernel sqrt+sums and resets state to 0 for the next graph replay.
// Grid 8 x 18 x 2 = 288 CTAs (~2/SM). Register double-buffered SMEM reads.
// ============================================================

#define THREADS 256
#define QPT 8            // queries per thread (4 packed pairs)
#define TCHUNK 911       // 18 chunks cover 16384 (18*911 = 16398)
#define NCHUNKS 18
#define MAXPTS 16384

__device__ unsigned g_min[2 * MAXPTS];   // zero-init BSS; holds ~bits(min dsq)

__device__ __forceinline__ unsigned long long pack2(float lo, float hi) {
    unsigned long long r;
    asm("mov.b64 %0, {%1, %2};" : "=l"(r) : "f"(lo), "f"(hi));
    return r;
}
__device__ __forceinline__ void unpack2(unsigned long long v, float& lo, float& hi) {
    asm("mov.b64 {%0, %1}, %2;" : "=f"(lo), "=f"(hi) : "l"(v));
}
__device__ __forceinline__ unsigned long long fma2(unsigned long long a,
                                                   unsigned long long b,
                                                   unsigned long long c) {
    unsigned long long d;
    asm("fma.rn.f32x2 %0, %1, %2, %3;" : "=l"(d) : "l"(a), "l"(b), "l"(c));
    return d;
}

__global__ void __launch_bounds__(THREADS)
chamfer_min_kernel(const float* __restrict__ A, const float* __restrict__ B,
                   int N, int M)
{
    const int tid = threadIdx.x;
    const int dir = blockIdx.z;
    const float* __restrict__ P = dir ? B : A;   // queries
    const float* __restrict__ T = dir ? A : B;   // targets
    const int nq = dir ? M : N;
    const int nt = dir ? N : M;
    unsigned* minarr = g_min + dir * MAXPTS;

    // per target: {bx,bx},{by,by} | {bz,bz},{nhb,nhb}; +1 pad entry for prefetch
    __shared__ ulonglong2 sv[(TCHUNK + 1) * 2];

    const int tbase = blockIdx.y * TCHUNK;
    if (tbase >= nt) return;
    const int nload = min(TCHUNK, nt - tbase);

    for (int j = tid; j < nload; j += THREADS) {
        float bx = T[(tbase + j) * 3 + 0];
        float by = T[(tbase + j) * 3 + 1];
        float bz = T[(tbase + j) * 3 + 2];
        float nhb = -0.5f * fmaf(bx, bx, fmaf(by, by, bz * bz));
        sv[2 * j]     = make_ulonglong2(pack2(bx, bx), pack2(by, by));
        sv[2 * j + 1] = make_ulonglong2(pack2(bz, bz), pack2(nhb, nhb));
    }
    if (tid == 0) {   // pad so prefetch of j+1 is always in-bounds
        sv[2 * nload]     = make_ulonglong2(0ull, 0ull);
        sv[2 * nload + 1] = make_ulonglong2(0ull, 0ull);
    }
    __syncthreads();

    // register-resident queries, packed in pairs
    const int qbase = blockIdx.x * (THREADS * QPT) + tid;
    float qfx[QPT], qfy[QPT], qfz[QPT], qn[QPT], ms[QPT];
    #pragma unroll
    for (int q = 0; q < QPT; q++) {
        int qi = qbase + q * THREADS;
        int base = (qi < nq ? qi : 0) * 3;
        qfx[q] = P[base + 0];
        qfy[q] = P[base + 1];
        qfz[q] = P[base + 2];
        qn[q] = fmaf(qfx[q], qfx[q], fmaf(qfy[q], qfy[q], qfz[q] * qfz[q]));
        ms[q] = -CUDART_INF_F;
    }
    unsigned long long qx[QPT / 2], qy[QPT / 2], qz[QPT / 2];
    #pragma unroll
    for (int p = 0; p < QPT / 2; p++) {
        qx[p] = pack2(qfx[2 * p], qfx[2 * p + 1]);
        qy[p] = pack2(qfy[2 * p], qfy[2 * p + 1]);
        qz[p] = pack2(qfz[2 * p], qfz[2 * p + 1]);
    }

    // main loop: register double-buffer hides LDS latency behind one
    // full iteration of math (12 FFMA2 + 8 FMNMX per target).
    ulonglong2 c0 = sv[0], c1 = sv[1];
    #pragma unroll 2
    for (int j = 0; j < nload; j++) {
        const ulonglong2 n0 = sv[2 * (j + 1)];       // prefetch next target
        const ulonglong2 n1 = sv[2 * (j + 1) + 1];
        #pragma unroll
        for (int p = 0; p < QPT / 2; p++) {
            unsigned long long t = fma2(qz[p], c1.x, c1.y);  // qz*bz - .5|b|^2
            t = fma2(qy[p], c0.y, t);
            t = fma2(qx[p], c0.x, t);                        // s
            float s0, s1;
            unpack2(t, s0, s1);
            ms[2 * p]     = fmaxf(ms[2 * p],     s0);
            ms[2 * p + 1] = fmaxf(ms[2 * p + 1], s1);
        }
        c0 = n0; c1 = n1;
    }

    // dsq = max(qn - 2*max_s, 0); cross-CTA min == atomicMax of ~bits (dsq >= 0)
    #pragma unroll
    for (int q = 0; q < QPT; q++) {
        int qi = qbase + q * THREADS;
        if (qi < nq) {
            float dsq = fmaxf(fmaf(-2.0f, ms[q], qn[q]), 0.0f);
            atomicMax(&minarr[qi], ~(unsigned)__float_as_int(dsq));
        }
    }
}

__global__ void __launch_bounds__(1024)
chamfer_reduce_kernel(float* __restrict__ out, int total)
{
    __shared__ float ssum[32];
    float acc = 0.0f;
    for (int i = threadIdx.x; i < total; i += 1024) {
        unsigned u = g_min[i];
        acc += sqrtf(__int_as_float((int)~u));
        g_min[i] = 0u;                     // reset for next graph replay
    }

    #pragma unroll
    for (int o = 16; o > 0; o >>= 1)
        acc += __shfl_down_sync(0xFFFFFFFFu, acc, o);
    if ((threadIdx.x & 31) == 0) ssum[threadIdx.x >> 5] = acc;
    __syncthreads();
    if (threadIdx.x < 32) {
        float v = ssum[threadIdx.x];
        #pragma unroll
        for (int o = 16; o > 0; o >>= 1)
            v += __shfl_down_sync(0xFFFFFFFFu, v, o);
        if (threadIdx.x == 0) out[0] = v * 0.001f;
    }
}

extern "C" void kernel_launch(void* const* d_in, const int* in_sizes, int n_in,
                              void* d_out, int out_size)
{
    const float* A = (const float*)d_in[0];   // target_pc [N,3]
    const float* B = (const float*)d_in[1];   // output_pc [M,3]
    const int N = in_sizes[0] / 3;
    const int M = in_sizes[1] / 3;

    dim3 grid(8, NCHUNKS, 2);                 // 8*18*2 = 288 CTAs (~2/SM)
    chamfer_min_kernel<<<grid, THREADS>>>(A, B, N, M);

    chamfer_reduce_kernel<<<1, 1024>>>((float*)d_out, N + M);
}

// round 6
// speedup vs baseline: 1.8039x; 1.1398x over previous
#include <cuda_runtime.h>
#include <math_constants.h>

// ============================================================
// ChamferLoss, 3 launches.
// s = q.b - 0.5|b|^2 via fma.rn.f32x2 (2 queries/op); min d^2 = qn - 2*max_j s.
// QPT=16: 24 FFMA2 / 45 issues per (warp,target) -> fma-pipe-bound.
// Cross-CTA min: atomicMax on ~bits(dsq) (identity 0 -> no init kernel);
// 2-stage parallel reduce resets state to 0 for the next graph replay.
// Grid 4 x 37 x 2 = 296 CTAs = exactly 2/SM on 148 SMs.
// ============================================================

#define THREADS 256
#define QPT 16           // queries per thread (8 packed pairs)
#define QPAIRS (QPT / 2)
#define QBLOCKS 4        // 4 * 256 * 16 = 16384
#define TCHUNK 443       // 37 chunks cover 16384 (37*443 = 16391)
#define NCHUNKS 37
#define MAXPTS 16384
#define RED_CTAS 64
#define RED_THREADS 256

__device__ unsigned g_min[2 * MAXPTS];   // zero-init BSS; holds ~bits(min dsq)
__device__ float g_part[RED_CTAS];

__device__ __forceinline__ unsigned long long pack2(float lo, float hi) {
    unsigned long long r;
    asm("mov.b64 %0, {%1, %2};" : "=l"(r) : "f"(lo), "f"(hi));
    return r;
}
__device__ __forceinline__ void unpack2(unsigned long long v, float& lo, float& hi) {
    asm("mov.b64 {%0, %1}, %2;" : "=f"(lo), "=f"(hi) : "l"(v));
}
__device__ __forceinline__ unsigned long long fma2(unsigned long long a,
                                                   unsigned long long b,
                                                   unsigned long long c) {
    unsigned long long d;
    asm("fma.rn.f32x2 %0, %1, %2, %3;" : "=l"(d) : "l"(a), "l"(b), "l"(c));
    return d;
}

__global__ void __launch_bounds__(THREADS, 2)
chamfer_min_kernel(const float* __restrict__ A, const float* __restrict__ B,
                   int N, int M)
{
    const int tid = threadIdx.x;
    const int dir = blockIdx.z;
    const float* __restrict__ P = dir ? B : A;   // queries
    const float* __restrict__ T = dir ? A : B;   // targets
    const int nq = dir ? M : N;
    const int nt = dir ? N : M;
    unsigned* minarr = g_min + dir * MAXPTS;

    // per target: {bx,bx},{by,by} | {bz,bz},{nhb,nhb}; +1 pad entry for prefetch
    __shared__ ulonglong2 sv[(TCHUNK + 1) * 2];

    const int tbase = blockIdx.y * TCHUNK;
    if (tbase >= nt) return;
    const int nload = min(TCHUNK, nt - tbase);

    for (int j = tid; j < nload; j += THREADS) {
        float bx = T[(tbase + j) * 3 + 0];
        float by = T[(tbase + j) * 3 + 1];
        float bz = T[(tbase + j) * 3 + 2];
        float nhb = -0.5f * fmaf(bx, bx, fmaf(by, by, bz * bz));
        sv[2 * j]     = make_ulonglong2(pack2(bx, bx), pack2(by, by));
        sv[2 * j + 1] = make_ulonglong2(pack2(bz, bz), pack2(nhb, nhb));
    }
    if (tid == 0) {   // pad so prefetch of j+1 is always in-bounds
        sv[2 * nload]     = make_ulonglong2(0ull, 0ull);
        sv[2 * nload + 1] = make_ulonglong2(0ull, 0ull);
    }
    __syncthreads();

    // register-resident queries, packed in pairs
    const int qbase = blockIdx.x * (THREADS * QPT) + tid;
    unsigned long long qx[QPAIRS], qy[QPAIRS], qz[QPAIRS];
    float qn[QPT], ms[QPT];
    #pragma unroll
    for (int p = 0; p < QPAIRS; p++) {
        float fx[2], fy[2], fz[2];
        #pragma unroll
        for (int h = 0; h < 2; h++) {
            int q = 2 * p + h;
            int qi = qbase + q * THREADS;
            int base = (qi < nq ? qi : 0) * 3;
            fx[h] = P[base + 0];
            fy[h] = P[base + 1];
            fz[h] = P[base + 2];
            qn[q] = fmaf(fx[h], fx[h], fmaf(fy[h], fy[h], fz[h] * fz[h]));
            ms[q] = -CUDART_INF_F;
        }
        qx[p] = pack2(fx[0], fx[1]);
        qy[p] = pack2(fy[0], fy[1]);
        qz[p] = pack2(fz[0], fz[1]);
    }

    // main loop: register double-buffer; 24 FFMA2 + 16 FMNMX + 2 LDS per target
    ulonglong2 c0 = sv[0], c1 = sv[1];
    for (int j = 0; j < nload; j++) {
        const ulonglong2 n0 = sv[2 * (j + 1)];       // prefetch next target
        const ulonglong2 n1 = sv[2 * (j + 1) + 1];
        #pragma unroll
        for (int p = 0; p < QPAIRS; p++) {
            unsigned long long t = fma2(qz[p], c1.x, c1.y);  // qz*bz - .5|b|^2
            t = fma2(qy[p], c0.y, t);
            t = fma2(qx[p], c0.x, t);                        // s
            float s0, s1;
            unpack2(t, s0, s1);
            ms[2 * p]     = fmaxf(ms[2 * p],     s0);
            ms[2 * p + 1] = fmaxf(ms[2 * p + 1], s1);
        }
        c0 = n0; c1 = n1;
    }

    // dsq = max(qn - 2*max_s, 0); cross-CTA min == atomicMax of ~bits (dsq >= 0)
    #pragma unroll
    for (int q = 0; q < QPT; q++) {
        int qi = qbase + q * THREADS;
        if (qi < nq) {
            float dsq = fmaxf(fmaf(-2.0f, ms[q], qn[q]), 0.0f);
            atomicMax(&minarr[qi], ~(unsigned)__float_as_int(dsq));
        }
    }
}

// Stage 1: 64 CTAs, each sums sqrt over a fixed 512-element slice and
// resets g_min to 0 for the next graph replay. Deterministic partition.
__global__ void __launch_bounds__(RED_THREADS)
chamfer_reduce1_kernel(int total)
{
    __shared__ float ssum[RED_THREADS / 32];
    const int per = (total + RED_CTAS - 1) / RED_CTAS;     // 512
    const int base = blockIdx.x * per;
    const int end = min(base + per, total);

    float acc = 0.0f;
    for (int i = base + threadIdx.x; i < end; i += RED_THREADS) {
        unsigned u = g_min[i];
        acc += sqrtf(__int_as_float((int)~u));
        g_min[i] = 0u;
    }
    #pragma unroll
    for (int o = 16; o > 0; o >>= 1)
        acc += __shfl_down_sync(0xFFFFFFFFu, acc, o);
    if ((threadIdx.x & 31) == 0) ssum[threadIdx.x >> 5] = acc;
    __syncthreads();
    if (threadIdx.x == 0) {
        float v = 0.0f;
        #pragma unroll
        for (int w = 0; w < RED_THREADS / 32; w++) v += ssum[w];
        g_part[blockIdx.x] = v;
    }
}

// Stage 2: one warp folds the 64 partials.
__global__ void chamfer_reduce2_kernel(float* __restrict__ out)
{
    float acc = 0.0f;
    #pragma unroll
    for (int k = 0; k < RED_CTAS / 32; k++)
        acc += g_part[threadIdx.x + 32 * k];
    #pragma unroll
    for (int o = 16; o > 0; o >>= 1)
        acc += __shfl_down_sync(0xFFFFFFFFu, acc, o);
    if (threadIdx.x == 0) out[0] = acc * 0.001f;
}

extern "C" void kernel_launch(void* const* d_in, const int* in_sizes, int n_in,
                              void* d_out, int out_size)
{
    const float* A = (const float*)d_in[0];   // target_pc [N,3]
    const float* B = (const float*)d_in[1];   // output_pc [M,3]
    const int N = in_sizes[0] / 3;
    const int M = in_sizes[1] / 3;

    dim3 grid(QBLOCKS, NCHUNKS, 2);           // 4*37*2 = 296 CTAs = 2/SM
    chamfer_min_kernel<<<grid, THREADS>>>(A, B, N, M);

    chamfer_reduce1_kernel<<<RED_CTAS, RED_THREADS>>>(N + M);
    chamfer_reduce2_kernel<<<1, 32>>>((float*)d_out);
}